// round 9
// baseline (speedup 1.0000x reference)
#include <cuda_runtime.h>
#include <cstdint>

// Problem dims (fixed by the dataset's setup_inputs)
#define C_   128
#define H_   56
#define W_   56
#define HW_  3136
#define TOTAL_ (16 * 128 * 3136)

#define NPAIR_BC  1568                    // HW/2 pixel-pairs per (b,c)
#define NPAIR_TOT (16 * 128 * NPAIR_BC)   // 3,211,264
#define TPB 256

// set.ge -> -1 (true) / 0 (false): single SASS FSET, no predication
__device__ __forceinline__ int setge(float a, float b) {
    int r;
    asm("set.ge.s32.f32 %0, %1, %2;" : "=r"(r) : "f"(a), "f"(b));
    return r;
}

// ---- packed-rank machinery (see round-8 layout) ----------------------------
// w[r]: byte0 = RA(r,1), byte1 = RA(r,2), byte2 = RB(r,1), byte3 = RB(r,2)
// wa:   byte r = RA(r,0)          wb: byte r = RB(r,3)
// Counter init = 8 - e; every prefix value stays in [0,8] -> bytes never
// under/overflow, so whole-word add/sub of packed constants is exact.
__host__ __device__ constexpr int kofA(int wi, int r, int c) {
    return (c == 1 && wi == r) ? 1
         : (c == 2 && wi == r) ? (1 << 8)
         : (c == 0 && wi == 3) ? (1 << (8 * r))
         : 0;
}
__host__ __device__ constexpr int kofB(int wi, int r, int c) {
    return (c == 1 && wi == r) ? (1 << 16)
         : (c == 2 && wi == r) ? (1 << 24)
         : (c == 3 && wi == 4) ? (1 << (8 * r))
         : 0;
}
__host__ __device__ constexpr int kpair(int wi, int rX, int cX, int rY, int cY) {
    return ((cX <= 2 && cY <= 2) ? (kofA(wi, rX, cX) - kofA(wi, rY, cY)) : 0)
         + ((cX >= 1 && cY >= 1) ? (kofB(wi, rX, cX) - kofB(wi, rY, cY)) : 0);
}

#define PAIR(rX, cX, rY, cY)                                                  \
    {                                                                         \
        const int m = setge(v[rX][cX], v[rY][cY]);                            \
        { constexpr int K = kpair(0, rX, cX, rY, cY); if (K) w0 += m * K; }   \
        { constexpr int K = kpair(1, rX, cX, rY, cY); if (K) w1 += m * K; }   \
        { constexpr int K = kpair(2, rX, cX, rY, cY); if (K) w2 += m * K; }   \
        { constexpr int K = kpair(3, rX, cX, rY, cY); if (K) wa += m * K; }   \
        { constexpr int K = kpair(4, rX, cX, rY, cY); if (K) wb += m * K; }   \
    }

// within-row pairs (skip (0,3): not co-windowed)
#define WROW(r) PAIR(r,0,r,1) PAIR(r,0,r,2) PAIR(r,1,r,2) PAIR(r,1,r,3) PAIR(r,2,r,3)
// cross-row pairs: all 4x4 col combos except (0,3) and (3,0)
#define XROW(ra, rb)                                                          \
    PAIR(ra,0,rb,0) PAIR(ra,0,rb,1) PAIR(ra,0,rb,2)                           \
    PAIR(ra,1,rb,0) PAIR(ra,1,rb,1) PAIR(ra,1,rb,2) PAIR(ra,1,rb,3)           \
    PAIR(ra,2,rb,0) PAIR(ra,2,rb,1) PAIR(ra,2,rb,2) PAIR(ra,2,rb,3)           \
    PAIR(ra,3,rb,1) PAIR(ra,3,rb,2) PAIR(ra,3,rb,3)

__global__ __launch_bounds__(TPB)
void rrsvm_kernel(const float* __restrict__ x,
                  const float* __restrict__ s,
                  float* __restrict__ vout,
                  float* __restrict__ idxout)
{
    __shared__ float ssm[8][9];                              // per-warp rank weights
    __shared__ __align__(16) unsigned char stage8[8][576];   // byte index stage

    const int tid  = threadIdx.x;
    const int warp = tid >> 5;
    const int lane = tid & 31;
    const int t    = blockIdx.x * TPB + tid;          // pair id, exact grid

    const int bc = t / NPAIR_BC;                      // b*C + c
    const int q  = t - bc * NPAIR_BC;
    const int y  = q / 28;                            // output row
    const int xx = (q - y * 28) * 2;                  // left pixel col (even)

    // warp never straddles (b,c): NPAIR_BC = 1568 is a multiple of 32
    if (lane < 9)
        ssm[warp][lane] = __ldg(s + (bc & (C_ - 1)) * 9 + lane);
    __syncwarp();

    const float* __restrict__ xb = x + (size_t)bc * HW_;
    const bool pl = (xx > 0);          // col xx-1 valid
    const bool pr = (xx < W_ - 2);     // col xx+2 valid

    // 3 rows x 4 cols covering both 3x3 windows (zero padding = real values)
    float v[3][4];
#pragma unroll
    for (int rr = 0; rr < 3; rr++) {
        const int gy   = y + rr - 1;
        const bool rok = ((unsigned)gy < (unsigned)H_);
        const float* p = xb + gy * W_ + xx;
        v[rr][0] = (rok & pl) ? __ldg(p - 1) : 0.f;
        v[rr][1] = rok        ? __ldg(p)     : 0.f;
        v[rr][2] = rok        ? __ldg(p + 1) : 0.f;
        v[rr][3] = (rok & pr) ? __ldg(p + 2) : 0.f;
    }

    // packed rank accumulation (init = 8 - e per counter)
    int w0 = 7 | (6 << 8) | (8 << 16) | (7 << 24);
    int w1 = 4 | (3 << 8) | (5 << 16) | (4 << 24);
    int w2 = 1 | (0 << 8) | (2 << 16) | (1 << 24);
    int wa = 8 | (5 << 8) | (2 << 16);
    int wb = 6 | (3 << 8) | (0 << 16);

    WROW(0) WROW(1) WROW(2)
    XROW(0, 1) XROW(0, 2) XROW(1, 2)

    // extract the 9+9 ranks (bytes)
    int r0[9], r1[9];
    r0[0] =  wa        & 255;  r0[1] =  w0        & 255;  r0[2] = (w0 >> 8)  & 255;
    r0[3] = (wa >> 8)  & 255;  r0[4] =  w1        & 255;  r0[5] = (w1 >> 8)  & 255;
    r0[6] = (wa >> 16) & 255;  r0[7] =  w2        & 255;  r0[8] = (w2 >> 8)  & 255;
    r1[0] = (w0 >> 16) & 255;  r1[1] = (unsigned)w0 >> 24;  r1[2] =  wb        & 255;
    r1[3] = (w1 >> 16) & 255;  r1[4] = (unsigned)w1 >> 24;  r1[5] = (wb >> 8)  & 255;
    r1[6] = (w2 >> 16) & 255;  r1[7] = (unsigned)w2 >> 24;  r1[8] = (wb >> 16) & 255;

    // Values (gather s via multicast LDS) + byte index scatter into warp stage
    float acc0 = 0.f, acc1 = 0.f;
    unsigned char* st = &stage8[warp][lane * 18];
#pragma unroll
    for (int e = 0; e < 9; e++) {
        acc0 = fmaf(v[e/3][e%3],     ssm[warp][r0[e]], acc0);
        acc1 = fmaf(v[e/3][e%3 + 1], ssm[warp][r1[e]], acc1);
        st[r0[e]]     = (unsigned char)e;
        st[9 + r1[e]] = (unsigned char)e;
    }

    if (vout) {
        float2 o = make_float2(acc0, acc1);
        *(float2*)(vout + (size_t)bc * HW_ + y * W_ + xx) = o;   // 8B aligned
    }

    __syncwarp();
    if (idxout) {
        // warp's 64 pixels own a contiguous 576-float span of idxout.
        // Stage holds them as 576 bytes = 144 u32; each u32 expands to one
        // float4 via PRMT(0x4B0000|e) + FADD(-8388608) — exact for e in 0..8.
        const unsigned* sw  = (const unsigned*)stage8[warp];
        float4*         dst = (float4*)(idxout + (size_t)(t - lane) * 18);
#pragma unroll
        for (int k = 0; k < 5; k++) {
            if (k < 4 || lane < 16) {
                const int m = lane + 32 * k;
                const unsigned w = sw[m];
                float4 f;
                f.x = __uint_as_float(__byte_perm(w, 0x4B000000u, 0x7440)) - 8388608.f;
                f.y = __uint_as_float(__byte_perm(w, 0x4B000000u, 0x7441)) - 8388608.f;
                f.z = __uint_as_float(__byte_perm(w, 0x4B000000u, 0x7442)) - 8388608.f;
                f.w = __uint_as_float(__byte_perm(w, 0x4B000000u, 0x7443)) - 8388608.f;
                dst[m] = f;
            }
        }
    }
}

extern "C" void kernel_launch(void* const* d_in, const int* in_sizes, int n_in,
                              void* d_out, int out_size) {
    const float* x = (const float*)d_in[0];
    const float* s = (const float*)d_in[1];

    float* vout   = (float*)d_out;
    float* idxout = nullptr;

    // Reference returns (out[B,C,H,W], indices[B,C,H,W,9]); harness concatenates.
    if (out_size >= 10 * TOTAL_) {
        idxout = (float*)d_out + TOTAL_;   // [out | indices]
    } else if (out_size == 9 * TOTAL_) {
        idxout = (float*)d_out;            // indices only
        vout   = nullptr;
    }

    const int blocks = NPAIR_TOT / TPB;    // exact: 12544
    rrsvm_kernel<<<blocks, TPB>>>(x, s, vout, idxout);
}

// round 10
// speedup vs baseline: 1.0252x; 1.0252x over previous
#include <cuda_runtime.h>
#include <cstdint>

// Problem dims (fixed by the dataset's setup_inputs)
#define C_   128
#define H_   56
#define W_   56
#define HW_  3136
#define TOTAL_ (16 * 128 * 3136)

#define NQUAD_TOT (TOTAL_ / 4)    // 1,605,632 quads (4 horizontal px each)
#define TPB 256

// set.ge -> -1 (true) / 0 (false): single SASS FSET, no predication
__device__ __forceinline__ int setge(float a, float b) {
    int r;
    asm("set.ge.s32.f32 %0, %1, %2;" : "=r"(r) : "f"(a), "f"(b));
    return r;
}

// ---- packed-rank machinery, 4 windows --------------------------------------
// Tile cells (r, c), r in {0,1,2}, c in {0..5}. Window w (0..3) = cols w..w+2;
// element e = 3r + (c - w). 36 rank counters as bytes in 9 words:
//   A[r]: b0=R0(r,1) b1=R0(r,2) b2=R1(r,1) b3=R1(r,2)
//   B[r]: b0=R2(r,3) b1=R2(r,4) b2=R3(r,3) b3=R3(r,4)
//   C[r]: b0=R0(r,0) b1=R1(r,3) b2=R2(r,2) b3=R3(r,5)
// Init = 8 - e; every prefix stays in [0,8] (decrements bounded by #later
// elements, increments by #earlier), so bytes never carry and whole-word
// add of packed constants is exact. For pair X lex-before Y, mask m in
// {0,-1}: counter(X) += m, counter(Y) -= m, per window containing both.
__host__ __device__ constexpr int kof(int kind, int wi, int w, int r, int c) {
    return (r != wi) ? 0
        : (kind == 0) ? ((w==0&&c==1)?1 : (w==0&&c==2)?(1<<8)
                        :(w==1&&c==1)?(1<<16) : (w==1&&c==2)?(1<<24) : 0)
        : (kind == 1) ? ((w==2&&c==3)?1 : (w==2&&c==4)?(1<<8)
                        :(w==3&&c==3)?(1<<16) : (w==3&&c==4)?(1<<24) : 0)
        :               ((w==0&&c==0)?1 : (w==1&&c==3)?(1<<8)
                        :(w==2&&c==2)?(1<<16) : (w==3&&c==5)?(1<<24) : 0);
}
__host__ __device__ constexpr int kpair(int kind, int wi,
                                        int rX, int cX, int rY, int cY) {
    int s = 0;
    for (int w = 0; w < 4; w++)
        if (cX >= w && cX <= w + 2 && cY >= w && cY <= w + 2)
            s += kof(kind, wi, w, rX, cX) - kof(kind, wi, w, rY, cY);
    return s;
}

#define UPD(var, kind, wi, rX, cX, rY, cY)                                    \
    { constexpr int K = kpair(kind, wi, rX, cX, rY, cY); if (K) var += m * K; }

#define PAIR(rX, cX, rY, cY)                                                  \
    {                                                                         \
        const int m = setge(v[rX][cX], v[rY][cY]);                            \
        UPD(A0, 0, 0, rX, cX, rY, cY) UPD(A1, 0, 1, rX, cX, rY, cY)           \
        UPD(A2, 0, 2, rX, cX, rY, cY) UPD(B0, 1, 0, rX, cX, rY, cY)           \
        UPD(B1, 1, 1, rX, cX, rY, cY) UPD(B2, 1, 2, rX, cX, rY, cY)           \
        UPD(C0, 2, 0, rX, cX, rY, cY) UPD(C1, 2, 1, rX, cX, rY, cY)           \
        UPD(C2, 2, 2, rX, cX, rY, cY)                                         \
    }

// within-row co-windowed pairs (|dc| <= 2)
#define WROW(r)                                                               \
    PAIR(r,0,r,1) PAIR(r,0,r,2) PAIR(r,1,r,2) PAIR(r,1,r,3) PAIR(r,2,r,3)     \
    PAIR(r,2,r,4) PAIR(r,3,r,4) PAIR(r,3,r,5) PAIR(r,4,r,5)
// cross-row pairs, all col combos with |dc| <= 2
#define XROW(ra, rb)                                                          \
    PAIR(ra,0,rb,0) PAIR(ra,0,rb,1) PAIR(ra,0,rb,2)                           \
    PAIR(ra,1,rb,0) PAIR(ra,1,rb,1) PAIR(ra,1,rb,2) PAIR(ra,1,rb,3)           \
    PAIR(ra,2,rb,0) PAIR(ra,2,rb,1) PAIR(ra,2,rb,2) PAIR(ra,2,rb,3)           \
    PAIR(ra,2,rb,4)                                                           \
    PAIR(ra,3,rb,1) PAIR(ra,3,rb,2) PAIR(ra,3,rb,3) PAIR(ra,3,rb,4)           \
    PAIR(ra,3,rb,5)                                                           \
    PAIR(ra,4,rb,2) PAIR(ra,4,rb,3) PAIR(ra,4,rb,4) PAIR(ra,4,rb,5)           \
    PAIR(ra,5,rb,3) PAIR(ra,5,rb,4) PAIR(ra,5,rb,5)

__global__ __launch_bounds__(TPB)
void rrsvm_kernel(const float* __restrict__ x,
                  const float* __restrict__ s,
                  float* __restrict__ vout,
                  float* __restrict__ idxout)
{
    __shared__ float ssm[8][18];                        // 2 channels per warp
    __shared__ __align__(16) float stage[8][1152];      // per-warp idx staging

    const int tid  = threadIdx.x;
    const int warp = tid >> 5;
    const int lane = tid & 31;
    const int t    = blockIdx.x * TPB + tid;            // quad id, exact grid

    const int p0  = t * 4;                              // first pixel (global)
    const int bc  = p0 / HW_;                           // b*C + c (4 | HW_)
    const int rem = p0 - bc * HW_;
    const int y   = rem / W_;
    const int xx  = rem - y * W_;                       // multiple of 4

    // Warp can straddle at most one (b,c) boundary: two-channel s table.
    const int bcf = __shfl_sync(0xFFFFFFFFu, bc, 0);
    const int bcl = __shfl_sync(0xFFFFFFFFu, bc, 31);
    if (lane < 9)
        ssm[warp][lane] = __ldg(s + (bcf & (C_ - 1)) * 9 + lane);
    else if (lane < 18)
        ssm[warp][lane] = __ldg(s + (bcl & (C_ - 1)) * 9 + lane - 9);
    __syncwarp();
    const float* tb = ssm[warp] + ((bc != bcf) ? 9 : 0);

    const float* __restrict__ xb = x + (size_t)bc * HW_;
    const bool pl = (xx > 0);
    const bool pr = (xx < 52);

    // 3 rows x 6 cols covering the 4 windows (zero padding = real values)
    float v[3][6];
#pragma unroll
    for (int rr = 0; rr < 3; rr++) {
        const int gy   = y + rr - 1;
        const bool rok = ((unsigned)gy < (unsigned)H_);
        const float* p = xb + gy * W_ + xx;
        float4 m4 = make_float4(0.f, 0.f, 0.f, 0.f);
        if (rok) m4 = *(const float4*)p;                 // 16B aligned
        v[rr][1] = m4.x; v[rr][2] = m4.y; v[rr][3] = m4.z; v[rr][4] = m4.w;
        v[rr][0] = (rok & pl) ? __ldg(p - 1) : 0.f;
        v[rr][5] = (rok & pr) ? __ldg(p + 4) : 0.f;
    }

    // packed rank accumulation (init = 8 - e per counter)
    int A0 = 7 | (6 << 8) | (8 << 16) | (7 << 24);
    int A1 = 4 | (3 << 8) | (5 << 16) | (4 << 24);
    int A2 = 1 | (0 << 8) | (2 << 16) | (1 << 24);
    int B0 = A0, B1 = A1, B2 = A2;
    int C0 = 8 | (6 << 8) | (8 << 16) | (6 << 24);
    int C1 = 5 | (3 << 8) | (5 << 16) | (3 << 24);
    int C2 = 2 | (0 << 8) | (2 << 16) | (0 << 24);

    WROW(0) WROW(1) WROW(2)
    XROW(0, 1) XROW(0, 2) XROW(1, 2)

    const int WA[3] = {A0, A1, A2};
    const int WB[3] = {B0, B1, B2};
    const int WC[3] = {C0, C1, C2};

    // Values (gather s via LDS) + index scatter into warp stage.
    // Thread region = 36 floats at lane*36: bank = 4*lane + offset -> the
    // 8-apart lane groups conflict only on equal ranks (~1.3x avg).
    float accv[4];
    float* st = &stage[warp][lane * 36];
#pragma unroll
    for (int w = 0; w < 4; w++) {
        float acc = 0.f;
#pragma unroll
        for (int r = 0; r < 3; r++) {
            int q0, q1, q2;
            if (w == 0) {
                q0 =  WC[r]        & 255; q1 =  WA[r]        & 255; q2 = (WA[r] >> 8) & 255;
            } else if (w == 1) {
                q0 = (WA[r] >> 16) & 255; q1 = (unsigned)WA[r] >> 24; q2 = (WC[r] >> 8) & 255;
            } else if (w == 2) {
                q0 = (WC[r] >> 16) & 255; q1 =  WB[r]        & 255; q2 = (WB[r] >> 8) & 255;
            } else {
                q0 = (WB[r] >> 16) & 255; q1 = (unsigned)WB[r] >> 24; q2 = (unsigned)WC[r] >> 24;
            }
            acc = fmaf(v[r][w + 0], tb[q0], acc);
            acc = fmaf(v[r][w + 1], tb[q1], acc);
            acc = fmaf(v[r][w + 2], tb[q2], acc);
            st[9 * w + q0] = (float)(3 * r + 0);
            st[9 * w + q1] = (float)(3 * r + 1);
            st[9 * w + q2] = (float)(3 * r + 2);
        }
        accv[w] = acc;
    }

    if (vout) {
        float4 o = make_float4(accv[0], accv[1], accv[2], accv[3]);
        *(float4*)(vout + (size_t)p0) = o;               // 16B aligned
    }

    __syncwarp();
    if (idxout) {
        // warp's 128 pixels own a contiguous 1152-float (288 float4) span
        const float4* sf  = (const float4*)stage[warp];
        float4*       dst = (float4*)(idxout + (size_t)(t - lane) * 36);
#pragma unroll
        for (int k = 0; k < 9; k++)
            dst[lane + 32 * k] = sf[lane + 32 * k];
    }
}

extern "C" void kernel_launch(void* const* d_in, const int* in_sizes, int n_in,
                              void* d_out, int out_size) {
    const float* x = (const float*)d_in[0];
    const float* s = (const float*)d_in[1];

    float* vout   = (float*)d_out;
    float* idxout = nullptr;

    // Reference returns (out[B,C,H,W], indices[B,C,H,W,9]); harness concatenates.
    if (out_size >= 10 * TOTAL_) {
        idxout = (float*)d_out + TOTAL_;   // [out | indices]
    } else if (out_size == 9 * TOTAL_) {
        idxout = (float*)d_out;            // indices only
        vout   = nullptr;
    }

    const int blocks = NQUAD_TOT / TPB;    // exact: 6272
    rrsvm_kernel<<<blocks, TPB>>>(x, s, vout, idxout);
}

// round 11
// speedup vs baseline: 1.0394x; 1.0139x over previous
#include <cuda_runtime.h>
#include <cstdint>

// Problem dims (fixed by the dataset's setup_inputs)
#define C_   128
#define H_   56
#define W_   56
#define HW_  3136
#define TOTAL_ (16 * 128 * 3136)

#define NQUAD_TOT (TOTAL_ / 4)    // 1,605,632 quads (4 horizontal px each)
#define TPB 256

// set.ge -> -1 (true) / 0 (false): single SASS FSET, no predication
__device__ __forceinline__ int setge(float a, float b) {
    int r;
    asm("set.ge.s32.f32 %0, %1, %2;" : "=r"(r) : "f"(a), "f"(b));
    return r;
}

// ---- nibble-packed rank counters, 4 windows --------------------------------
// Tile cells (r, c), r in {0,1,2}, c in {0..5}. Window w (0..3) = cols w..w+2;
// element e = 3r + (c - w). Counter id = w*9 + e (0..35), packed 8 nibbles
// per word across 5 words: word = id>>3, nibble = id&7.
// Init = 8 - e. Every prefix value stays in [0,8] (decrements bounded by
// #later elements, increments by #earlier), so nibbles never carry/borrow
// and whole-word add of packed signed constants is exact (SWAR).
// For pair X lex-before Y, mask m in {0,-1}: counter(X) += m,
// counter(Y) -= m, per window containing both cells.
__host__ __device__ constexpr int nibK(int wi, int w, int r, int c) {
    int id = w * 9 + (3 * r + c - w);
    return ((id >> 3) == wi) ? (1 << (4 * (id & 7))) : 0;
}
__host__ __device__ constexpr int kpair(int wi, int rX, int cX, int rY, int cY) {
    int s = 0;
    for (int w = 0; w < 4; w++)
        if (cX >= w && cX <= w + 2 && cY >= w && cY <= w + 2)
            s += nibK(wi, w, rX, cX) - nibK(wi, w, rY, cY);
    return s;
}
__host__ __device__ constexpr int initw(int wi) {
    int v = 0;
    for (int id = wi * 8; id < wi * 8 + 8 && id < 36; id++)
        v |= (8 - (id % 9)) << (4 * (id & 7));
    return v;
}

#define PAIR(rX, cX, rY, cY)                                                  \
    {                                                                         \
        const int m = setge(v[rX][cX], v[rY][cY]);                            \
        { constexpr int K = kpair(0, rX, cX, rY, cY); if (K) w0 += m * K; }   \
        { constexpr int K = kpair(1, rX, cX, rY, cY); if (K) w1 += m * K; }   \
        { constexpr int K = kpair(2, rX, cX, rY, cY); if (K) w2 += m * K; }   \
        { constexpr int K = kpair(3, rX, cX, rY, cY); if (K) w3 += m * K; }   \
        { constexpr int K = kpair(4, rX, cX, rY, cY); if (K) w4 += m * K; }   \
    }

// within-row co-windowed pairs (|dc| <= 2)
#define WROW(r)                                                               \
    PAIR(r,0,r,1) PAIR(r,0,r,2) PAIR(r,1,r,2) PAIR(r,1,r,3) PAIR(r,2,r,3)     \
    PAIR(r,2,r,4) PAIR(r,3,r,4) PAIR(r,3,r,5) PAIR(r,4,r,5)
// cross-row pairs, all col combos with |dc| <= 2
#define XROW(ra, rb)                                                          \
    PAIR(ra,0,rb,0) PAIR(ra,0,rb,1) PAIR(ra,0,rb,2)                           \
    PAIR(ra,1,rb,0) PAIR(ra,1,rb,1) PAIR(ra,1,rb,2) PAIR(ra,1,rb,3)           \
    PAIR(ra,2,rb,0) PAIR(ra,2,rb,1) PAIR(ra,2,rb,2) PAIR(ra,2,rb,3)           \
    PAIR(ra,2,rb,4)                                                           \
    PAIR(ra,3,rb,1) PAIR(ra,3,rb,2) PAIR(ra,3,rb,3) PAIR(ra,3,rb,4)           \
    PAIR(ra,3,rb,5)                                                           \
    PAIR(ra,4,rb,2) PAIR(ra,4,rb,3) PAIR(ra,4,rb,4) PAIR(ra,4,rb,5)           \
    PAIR(ra,5,rb,3) PAIR(ra,5,rb,4) PAIR(ra,5,rb,5)

// rank extraction — w/e become literals after unroll; selector folds
#define WSEL_(i) ((i)==0 ? w0 : (i)==1 ? w1 : (i)==2 ? w2 : (i)==3 ? w3 : w4)
#define RANK_(w, e) ((WSEL_(((w)*9+(e)) >> 3) >> (4 * (((w)*9+(e)) & 7))) & 15)

// one window's value accumulate + index scatter (w literal)
#define DOWIN(w, out)                                                         \
    {                                                                         \
        float acc = 0.f;                                                      \
        int q;                                                                \
        q = RANK_(w,0); acc = fmaf(v[0][(w)+0], tb[q], acc); st[9*(w)+q] = 0.f; \
        q = RANK_(w,1); acc = fmaf(v[0][(w)+1], tb[q], acc); st[9*(w)+q] = 1.f; \
        q = RANK_(w,2); acc = fmaf(v[0][(w)+2], tb[q], acc); st[9*(w)+q] = 2.f; \
        q = RANK_(w,3); acc = fmaf(v[1][(w)+0], tb[q], acc); st[9*(w)+q] = 3.f; \
        q = RANK_(w,4); acc = fmaf(v[1][(w)+1], tb[q], acc); st[9*(w)+q] = 4.f; \
        q = RANK_(w,5); acc = fmaf(v[1][(w)+2], tb[q], acc); st[9*(w)+q] = 5.f; \
        q = RANK_(w,6); acc = fmaf(v[2][(w)+0], tb[q], acc); st[9*(w)+q] = 6.f; \
        q = RANK_(w,7); acc = fmaf(v[2][(w)+1], tb[q], acc); st[9*(w)+q] = 7.f; \
        q = RANK_(w,8); acc = fmaf(v[2][(w)+2], tb[q], acc); st[9*(w)+q] = 8.f; \
        out = acc;                                                            \
    }

__global__ __launch_bounds__(TPB, 5)
void rrsvm_kernel(const float* __restrict__ x,
                  const float* __restrict__ s,
                  float* __restrict__ vout,
                  float* __restrict__ idxout)
{
    __shared__ float ssm[8][18];                        // 2 channels per warp
    __shared__ __align__(16) float stage[8][1152];      // per-warp idx staging

    const int tid  = threadIdx.x;
    const int warp = tid >> 5;
    const int lane = tid & 31;
    const int t    = blockIdx.x * TPB + tid;            // quad id, exact grid

    const int p0  = t * 4;                              // first pixel (global)
    const int bc  = p0 / HW_;                           // b*C + c (4 | HW_)
    const int rem = p0 - bc * HW_;
    const int y   = rem / W_;
    const int xx  = rem - y * W_;                       // multiple of 4

    // Warp can straddle at most one (b,c) boundary: two-channel s table.
    const int bcf = __shfl_sync(0xFFFFFFFFu, bc, 0);
    const int bcl = __shfl_sync(0xFFFFFFFFu, bc, 31);
    if (lane < 9)
        ssm[warp][lane] = __ldg(s + (bcf & (C_ - 1)) * 9 + lane);
    else if (lane < 18)
        ssm[warp][lane] = __ldg(s + (bcl & (C_ - 1)) * 9 + lane - 9);
    __syncwarp();
    const float* tb = ssm[warp] + ((bc != bcf) ? 9 : 0);

    const float* __restrict__ xb = x + (size_t)bc * HW_;
    const bool pl = (xx > 0);
    const bool pr = (xx < 52);

    // 3 rows x 6 cols covering the 4 windows (zero padding = real values)
    float v[3][6];
#pragma unroll
    for (int rr = 0; rr < 3; rr++) {
        const int gy   = y + rr - 1;
        const bool rok = ((unsigned)gy < (unsigned)H_);
        const float* p = xb + gy * W_ + xx;
        float4 m4 = make_float4(0.f, 0.f, 0.f, 0.f);
        if (rok) m4 = *(const float4*)p;                 // 16B aligned
        v[rr][1] = m4.x; v[rr][2] = m4.y; v[rr][3] = m4.z; v[rr][4] = m4.w;
        v[rr][0] = (rok & pl) ? __ldg(p - 1) : 0.f;
        v[rr][5] = (rok & pr) ? __ldg(p + 4) : 0.f;
    }

    // nibble-packed rank accumulation
    int w0 = initw(0), w1 = initw(1), w2 = initw(2), w3 = initw(3), w4 = initw(4);

    WROW(0) WROW(1) WROW(2)
    XROW(0, 1) XROW(0, 2) XROW(1, 2)

    // Values (gather s via LDS) + index scatter into warp stage.
    // Thread region = 36 floats at lane*36: bank = 4*lane + offset -> the
    // 8-apart lane groups conflict only on equal ranks (~1.3x avg).
    float* st = &stage[warp][lane * 36];
    float a0, a1, a2, a3;
    DOWIN(0, a0)
    DOWIN(1, a1)
    DOWIN(2, a2)
    DOWIN(3, a3)

    if (vout) {
        float4 o = make_float4(a0, a1, a2, a3);
        *(float4*)(vout + (size_t)p0) = o;               // 16B aligned
    }

    __syncwarp();
    if (idxout) {
        // warp's 128 pixels own a contiguous 1152-float (288 float4) span
        const float4* sf  = (const float4*)stage[warp];
        float4*       dst = (float4*)(idxout + (size_t)(t - lane) * 36);
#pragma unroll
        for (int k = 0; k < 9; k++)
            dst[lane + 32 * k] = sf[lane + 32 * k];
    }
}

extern "C" void kernel_launch(void* const* d_in, const int* in_sizes, int n_in,
                              void* d_out, int out_size) {
    const float* x = (const float*)d_in[0];
    const float* s = (const float*)d_in[1];

    float* vout   = (float*)d_out;
    float* idxout = nullptr;

    // Reference returns (out[B,C,H,W], indices[B,C,H,W,9]); harness concatenates.
    if (out_size >= 10 * TOTAL_) {
        idxout = (float*)d_out + TOTAL_;   // [out | indices]
    } else if (out_size == 9 * TOTAL_) {
        idxout = (float*)d_out;            // indices only
        vout   = nullptr;
    }

    const int blocks = NQUAD_TOT / TPB;    // exact: 6272
    rrsvm_kernel<<<blocks, TPB>>>(x, s, vout, idxout);
}

// round 12
// speedup vs baseline: 1.0852x; 1.0441x over previous
#include <cuda_runtime.h>
#include <cstdint>

// Problem dims (fixed by the dataset's setup_inputs)
#define C_   128
#define H_   56
#define W_   56
#define HW_  3136
#define TOTAL_ (16 * 128 * 3136)

#define NQUAD_TOT (TOTAL_ / 4)    // 1,605,632 quads (4 horizontal px each)
#define TPB 256

// set.ge -> -1 (true) / 0 (false): single SASS FSET, no predication
__device__ __forceinline__ int setge(float a, float b) {
    int r;
    asm("set.ge.s32.f32 %0, %1, %2;" : "=r"(r) : "f"(a), "f"(b));
    return r;
}

// ---- nibble-packed rank counters, 4 windows (see round-11 proof) -----------
// Counter id = w*9 + e (0..35), nibble id&7 of word id>>3 (5 words).
// Init = 8 - e; every prefix stays in [0,8] -> nibbles never carry/borrow.
__host__ __device__ constexpr int nibK(int wi, int w, int r, int c) {
    int id = w * 9 + (3 * r + c - w);
    return ((id >> 3) == wi) ? (1 << (4 * (id & 7))) : 0;
}
__host__ __device__ constexpr int kpair(int wi, int rX, int cX, int rY, int cY) {
    int s = 0;
    for (int w = 0; w < 4; w++)
        if (cX >= w && cX <= w + 2 && cY >= w && cY <= w + 2)
            s += nibK(wi, w, rX, cX) - nibK(wi, w, rY, cY);
    return s;
}
__host__ __device__ constexpr int initw(int wi) {
    int v = 0;
    for (int id = wi * 8; id < wi * 8 + 8 && id < 36; id++)
        v |= (8 - (id % 9)) << (4 * (id & 7));
    return v;
}

#define PAIR(rX, cX, rY, cY)                                                  \
    {                                                                         \
        const int m = setge(v[rX][cX], v[rY][cY]);                            \
        { constexpr int K = kpair(0, rX, cX, rY, cY); if (K) w0 += m * K; }   \
        { constexpr int K = kpair(1, rX, cX, rY, cY); if (K) w1 += m * K; }   \
        { constexpr int K = kpair(2, rX, cX, rY, cY); if (K) w2 += m * K; }   \
        { constexpr int K = kpair(3, rX, cX, rY, cY); if (K) w3 += m * K; }   \
        { constexpr int K = kpair(4, rX, cX, rY, cY); if (K) w4 += m * K; }   \
    }

#define WROW(r)                                                               \
    PAIR(r,0,r,1) PAIR(r,0,r,2) PAIR(r,1,r,2) PAIR(r,1,r,3) PAIR(r,2,r,3)     \
    PAIR(r,2,r,4) PAIR(r,3,r,4) PAIR(r,3,r,5) PAIR(r,4,r,5)
#define XROW(ra, rb)                                                          \
    PAIR(ra,0,rb,0) PAIR(ra,0,rb,1) PAIR(ra,0,rb,2)                           \
    PAIR(ra,1,rb,0) PAIR(ra,1,rb,1) PAIR(ra,1,rb,2) PAIR(ra,1,rb,3)           \
    PAIR(ra,2,rb,0) PAIR(ra,2,rb,1) PAIR(ra,2,rb,2) PAIR(ra,2,rb,3)           \
    PAIR(ra,2,rb,4)                                                           \
    PAIR(ra,3,rb,1) PAIR(ra,3,rb,2) PAIR(ra,3,rb,3) PAIR(ra,3,rb,4)           \
    PAIR(ra,3,rb,5)                                                           \
    PAIR(ra,4,rb,2) PAIR(ra,4,rb,3) PAIR(ra,4,rb,4) PAIR(ra,4,rb,5)           \
    PAIR(ra,5,rb,3) PAIR(ra,5,rb,4) PAIR(ra,5,rb,5)

// rank extraction — w/e become literals after unroll; selector folds
#define WSEL_(i) ((i)==0 ? w0 : (i)==1 ? w1 : (i)==2 ? w2 : (i)==3 ? w3 : w4)
#define RANK_(w, e) ((WSEL_(((w)*9+(e)) >> 3) >> (4 * (((w)*9+(e)) & 7))) & 15)

// one window: value accumulate + byte index scatter (w literal)
#define DOWIN(w, out)                                                            \
    {                                                                            \
        float acc = 0.f;                                                         \
        int q;                                                                   \
        q = RANK_(w,0); acc = fmaf(v[0][(w)+0], tb[q], acc); st[9*(w)+q] = 0;    \
        q = RANK_(w,1); acc = fmaf(v[0][(w)+1], tb[q], acc); st[9*(w)+q] = 1;    \
        q = RANK_(w,2); acc = fmaf(v[0][(w)+2], tb[q], acc); st[9*(w)+q] = 2;    \
        q = RANK_(w,3); acc = fmaf(v[1][(w)+0], tb[q], acc); st[9*(w)+q] = 3;    \
        q = RANK_(w,4); acc = fmaf(v[1][(w)+1], tb[q], acc); st[9*(w)+q] = 4;    \
        q = RANK_(w,5); acc = fmaf(v[1][(w)+2], tb[q], acc); st[9*(w)+q] = 5;    \
        q = RANK_(w,6); acc = fmaf(v[2][(w)+0], tb[q], acc); st[9*(w)+q] = 6;    \
        q = RANK_(w,7); acc = fmaf(v[2][(w)+1], tb[q], acc); st[9*(w)+q] = 7;    \
        q = RANK_(w,8); acc = fmaf(v[2][(w)+2], tb[q], acc); st[9*(w)+q] = 8;    \
        out = acc;                                                               \
    }

__global__ __launch_bounds__(TPB, 5)
void rrsvm_kernel(const float* __restrict__ x,
                  const float* __restrict__ s,
                  float* __restrict__ vout,
                  float* __restrict__ idxout)
{
    __shared__ float ssm[8][18];                           // 2 channels per warp
    __shared__ __align__(16) unsigned char stage8[8][1152];  // byte idx stage

    const int tid  = threadIdx.x;
    const int warp = tid >> 5;
    const int lane = tid & 31;
    const int t    = blockIdx.x * TPB + tid;            // quad id, exact grid

    const int p0  = t * 4;                              // first pixel (global)
    const int bc  = p0 / HW_;                           // b*C + c (4 | HW_)
    const int rem = p0 - bc * HW_;
    const int y   = rem / W_;
    const int xx  = rem - y * W_;                       // multiple of 4

    // Warp can straddle at most one (b,c) boundary: two-channel s table.
    const int bcf = __shfl_sync(0xFFFFFFFFu, bc, 0);
    const int bcl = __shfl_sync(0xFFFFFFFFu, bc, 31);
    if (lane < 9)
        ssm[warp][lane] = __ldg(s + (bcf & (C_ - 1)) * 9 + lane);
    else if (lane < 18)
        ssm[warp][lane] = __ldg(s + (bcl & (C_ - 1)) * 9 + lane - 9);
    __syncwarp();
    const float* tb = ssm[warp] + ((bc != bcf) ? 9 : 0);

    const float* __restrict__ xb = x + (size_t)bc * HW_;

    // 3 rows x 6 cols covering the 4 windows. Interior 4 via one float4;
    // edges come from the horizontally-adjacent lane's float4 (same row,
    // same channel whenever xx>0 / xx<52 — padding zeros propagate because
    // m4 is zeroed for OOB rows). Only warp-boundary lanes do fixup loads.
    float v[3][6];
#pragma unroll
    for (int rr = 0; rr < 3; rr++) {
        const int gy   = y + rr - 1;
        const bool rok = ((unsigned)gy < (unsigned)H_);
        const float* p = xb + gy * W_ + xx;
        float4 m4 = make_float4(0.f, 0.f, 0.f, 0.f);
        if (rok) m4 = *(const float4*)p;                 // 16B aligned
        v[rr][1] = m4.x; v[rr][2] = m4.y; v[rr][3] = m4.z; v[rr][4] = m4.w;

        float left  = __shfl_up_sync(0xFFFFFFFFu, m4.w, 1);
        float right = __shfl_down_sync(0xFFFFFFFFu, m4.x, 1);
        if (lane == 0  && xx > 0)  left  = rok ? __ldg(p - 1) : 0.f;
        if (lane == 31 && xx < 52) right = rok ? __ldg(p + 4) : 0.f;
        v[rr][0] = (xx == 0)  ? 0.f : left;
        v[rr][5] = (xx == 52) ? 0.f : right;
    }

    // nibble-packed rank accumulation
    int w0 = initw(0), w1 = initw(1), w2 = initw(2), w3 = initw(3), w4 = initw(4);

    WROW(0) WROW(1) WROW(2)
    XROW(0, 1) XROW(0, 2) XROW(1, 2)

    // Values (s-gather: <=9 distinct words in distinct banks -> multicast,
    // conflict-free) + byte index scatter (36B/lane regions -> lanes occupy
    // disjoint 9-word spans, near-conflict-free).
    unsigned char* st = &stage8[warp][lane * 36];
    float a0, a1, a2, a3;
    DOWIN(0, a0)
    DOWIN(1, a1)
    DOWIN(2, a2)
    DOWIN(3, a3)

    if (vout) {
        float4 o = make_float4(a0, a1, a2, a3);
        *(float4*)(vout + (size_t)p0) = o;               // 16B aligned
    }

    __syncwarp();
    if (idxout) {
        // warp's 128 pixels = 1152 idx floats, staged as 1152 bytes = 288 u32.
        // Each u32 -> float4 via PRMT(0x4B0000|e) + FADD(-8388608): exact for
        // e in 0..8 (verified round 9). 9 conflict-free LDS.32 per lane.
        const unsigned* sw  = (const unsigned*)stage8[warp];
        float4*         dst = (float4*)(idxout + (size_t)(t - lane) * 36);
#pragma unroll
        for (int k = 0; k < 9; k++) {
            const int m = lane + 32 * k;
            const unsigned w = sw[m];
            float4 f;
            f.x = __uint_as_float(__byte_perm(w, 0x4B000000u, 0x7440)) - 8388608.f;
            f.y = __uint_as_float(__byte_perm(w, 0x4B000000u, 0x7441)) - 8388608.f;
            f.z = __uint_as_float(__byte_perm(w, 0x4B000000u, 0x7442)) - 8388608.f;
            f.w = __uint_as_float(__byte_perm(w, 0x4B000000u, 0x7443)) - 8388608.f;
            dst[m] = f;
        }
    }
}

extern "C" void kernel_launch(void* const* d_in, const int* in_sizes, int n_in,
                              void* d_out, int out_size) {
    const float* x = (const float*)d_in[0];
    const float* s = (const float*)d_in[1];

    float* vout   = (float*)d_out;
    float* idxout = nullptr;

    // Reference returns (out[B,C,H,W], indices[B,C,H,W,9]); harness concatenates.
    if (out_size >= 10 * TOTAL_) {
        idxout = (float*)d_out + TOTAL_;   // [out | indices]
    } else if (out_size == 9 * TOTAL_) {
        idxout = (float*)d_out;            // indices only
        vout   = nullptr;
    }

    const int blocks = NQUAD_TOT / TPB;    // exact: 6272
    rrsvm_kernel<<<blocks, TPB>>>(x, s, vout, idxout);
}